// round 1
// baseline (speedup 1.0000x reference)
#include <cuda_runtime.h>

#define TPB 128

__global__ void pae_kernel(
    const float* __restrict__ g_center,   // [P,1,3]
    const float* __restrict__ g_other,    // [P,16,3]
    const float* __restrict__ g_w1,       // [6,3,16]
    const float* __restrict__ g_b1,       // [6,16]
    const float* __restrict__ g_w2,       // [6,16,32]
    const float* __restrict__ g_b2,       // [6,32]
    const float* __restrict__ g_wp1,      // [32,64]
    const float* __restrict__ g_wpb1,     // [64]
    const float* __restrict__ g_wp2,      // [64,32]
    const float* __restrict__ g_wpb2,     // [32]
    float* __restrict__ g_out,            // [P,32]
    int P)
{
    __shared__ __align__(16) float s_w1[288];     // [6][3][16]
    __shared__ __align__(16) float s_b1[96];      // [6][16]
    __shared__ __align__(16) float s_w2[3072];    // [6][16][32]
    __shared__ __align__(16) float s_b2[192];     // [6][32]
    __shared__ __align__(16) float s_wp1t[2048];  // [64][32] transposed
    __shared__ __align__(16) float s_wpb1[64];
    __shared__ __align__(16) float s_wp2[2048];   // [64][32]
    __shared__ __align__(16) float s_wpb2[32];

    const int tid = threadIdx.x;
    for (int i = tid; i < 288;  i += TPB) s_w1[i] = g_w1[i];
    for (int i = tid; i < 96;   i += TPB) s_b1[i] = g_b1[i];
    for (int i = tid; i < 3072; i += TPB) s_w2[i] = g_w2[i];
    for (int i = tid; i < 192;  i += TPB) s_b2[i] = g_b2[i];
    for (int i = tid; i < 2048; i += TPB) {
        int c = i >> 6, j = i & 63;        // g_wp1 is [32][64]
        s_wp1t[j * 32 + c] = g_wp1[i];
    }
    for (int i = tid; i < 64;   i += TPB) s_wpb1[i] = g_wpb1[i];
    for (int i = tid; i < 2048; i += TPB) s_wp2[i] = g_wp2[i];
    for (int i = tid; i < 32;   i += TPB) s_wpb2[i] = g_wpb2[i];
    __syncthreads();

    const int p = blockIdx.x * TPB + tid;
    if (p >= P) return;

    const float cx = g_center[p * 3 + 0];
    const float cy = g_center[p * 3 + 1];
    const float cz = g_center[p * 3 + 2];

    // ---- q = MLP0(center) ----
    float q[32];
    {
        #pragma unroll
        for (int c = 0; c < 32; ++c) q[c] = s_b2[c];
        #pragma unroll 2
        for (int j = 0; j < 16; ++j) {
            float z = s_b1[j] + cx * s_w1[j] + cy * s_w1[16 + j] + cz * s_w1[32 + j];
            float h = fmaxf(z, 0.01f * z);
            const float4* w = (const float4*)&s_w2[j * 32];
            #pragma unroll
            for (int c4 = 0; c4 < 8; ++c4) {
                float4 ww = w[c4];
                int c = c4 * 4;
                q[c + 0] = fmaf(h, ww.x, q[c + 0]);
                q[c + 1] = fmaf(h, ww.y, q[c + 1]);
                q[c + 2] = fmaf(h, ww.z, q[c + 2]);
                q[c + 3] = fmaf(h, ww.w, q[c + 3]);
            }
        }
    }

    float acc[32];
    #pragma unroll
    for (int c = 0; c < 32; ++c) acc[c] = 0.0f;

    const float* obase = g_other + p * 48;
    float nx0 = 0.f, nx1 = 0.f, nx2 = 0.f;   // prefetched neighbor coords

    for (int r = 0; r < 17; ++r) {
        float x0, x1, x2, d0, d1, d2;
        int mk, mv;
        if (r == 0) {
            x0 = cx; x1 = cy; x2 = cz;
            d0 = 0.f; d1 = 0.f; d2 = 0.f;
            mk = 1; mv = 2;
        } else {
            x0 = nx0; x1 = nx1; x2 = nx2;
            d0 = cx - x0; d1 = cy - x1; d2 = cz - x2;
            mk = 3; mv = 4;
        }
        // prefetch neighbor for row r+1 (neighbor index r)
        if (r < 16) {
            const float* op = obase + r * 3;
            nx0 = op[0]; nx1 = op[1]; nx2 = op[2];
        }

        const float* w1k = s_w1 + mk * 48;  const float* b1k = s_b1 + mk * 16;
        const float* w1v = s_w1 + mv * 48;  const float* b1v = s_b1 + mv * 16;
        const float* w1p = s_w1 + 5 * 48;   const float* b1p = s_b1 + 5 * 16;
        const float* w2k = s_w2 + mk * 512;
        const float* w2v = s_w2 + mv * 512;
        const float* w2p = s_w2 + 5 * 512;

        // ---- t = q - k + pos ; u = v + pos (biases first, hidden folded in) ----
        float t[32], u[32];
        {
            const float* b2k = s_b2 + mk * 32;
            const float* b2v = s_b2 + mv * 32;
            const float* b2p = s_b2 + 5 * 32;
            #pragma unroll
            for (int c = 0; c < 32; ++c) {
                float bp = b2p[c];
                t[c] = q[c] - b2k[c] + bp;
                u[c] = b2v[c] + bp;
            }
        }
        #pragma unroll 2
        for (int j = 0; j < 16; ++j) {
            float zk = b1k[j] + x0 * w1k[j] + x1 * w1k[16 + j] + x2 * w1k[32 + j];
            float zv = b1v[j] + x0 * w1v[j] + x1 * w1v[16 + j] + x2 * w1v[32 + j];
            float zp = b1p[j] + d0 * w1p[j] + d1 * w1p[16 + j] + d2 * w1p[32 + j];
            float hk = fmaxf(zk, 0.01f * zk);
            float hv = fmaxf(zv, 0.01f * zv);
            float hp = fmaxf(zp, 0.01f * zp);
            const float4* wk = (const float4*)&w2k[j * 32];
            const float4* wv = (const float4*)&w2v[j * 32];
            const float4* wp = (const float4*)&w2p[j * 32];
            #pragma unroll
            for (int c4 = 0; c4 < 8; ++c4) {
                float4 a = wk[c4], b = wv[c4], pw = wp[c4];
                int c = c4 * 4;
                t[c + 0] = fmaf(-hk, a.x, fmaf(hp, pw.x, t[c + 0]));
                u[c + 0] = fmaf( hv, b.x, fmaf(hp, pw.x, u[c + 0]));
                t[c + 1] = fmaf(-hk, a.y, fmaf(hp, pw.y, t[c + 1]));
                u[c + 1] = fmaf( hv, b.y, fmaf(hp, pw.y, u[c + 1]));
                t[c + 2] = fmaf(-hk, a.z, fmaf(hp, pw.z, t[c + 2]));
                u[c + 2] = fmaf( hv, b.z, fmaf(hp, pw.z, u[c + 2]));
                t[c + 3] = fmaf(-hk, a.w, fmaf(hp, pw.w, t[c + 3]));
                u[c + 3] = fmaf( hv, b.w, fmaf(hp, pw.w, u[c + 3]));
            }
        }

        // ---- fea_weight = WP(t): 32 -> 64 (leaky) -> 32 ----
        float fw[32];
        #pragma unroll
        for (int c = 0; c < 32; ++c) fw[c] = s_wpb2[c];

        #pragma unroll 4
        for (int j = 0; j < 64; ++j) {
            float z0 = s_wpb1[j], z1 = 0.f, z2 = 0.f, z3 = 0.f;
            const float4* w = (const float4*)&s_wp1t[j * 32];
            #pragma unroll
            for (int c4 = 0; c4 < 8; ++c4) {
                float4 ww = w[c4];
                int c = c4 * 4;
                z0 = fmaf(t[c + 0], ww.x, z0);
                z1 = fmaf(t[c + 1], ww.y, z1);
                z2 = fmaf(t[c + 2], ww.z, z2);
                z3 = fmaf(t[c + 3], ww.w, z3);
            }
            float z = (z0 + z1) + (z2 + z3);
            float g = fmaxf(z, 0.01f * z);
            const float4* w2 = (const float4*)&s_wp2[j * 32];
            #pragma unroll
            for (int c4 = 0; c4 < 8; ++c4) {
                float4 ww = w2[c4];
                int c = c4 * 4;
                fw[c + 0] = fmaf(g, ww.x, fw[c + 0]);
                fw[c + 1] = fmaf(g, ww.y, fw[c + 1]);
                fw[c + 2] = fmaf(g, ww.z, fw[c + 2]);
                fw[c + 3] = fmaf(g, ww.w, fw[c + 3]);
            }
        }

        // ---- channel softmax, weighted accumulate ----
        float m0 = fw[0], m1 = fw[1], m2 = fw[2], m3 = fw[3];
        #pragma unroll
        for (int c = 4; c < 32; c += 4) {
            m0 = fmaxf(m0, fw[c + 0]);
            m1 = fmaxf(m1, fw[c + 1]);
            m2 = fmaxf(m2, fw[c + 2]);
            m3 = fmaxf(m3, fw[c + 3]);
        }
        float m = fmaxf(fmaxf(m0, m1), fmaxf(m2, m3));
        float s0 = 0.f, s1 = 0.f, s2 = 0.f, s3 = 0.f;
        #pragma unroll
        for (int c = 0; c < 32; c += 4) {
            fw[c + 0] = __expf(fw[c + 0] - m);  s0 += fw[c + 0];
            fw[c + 1] = __expf(fw[c + 1] - m);  s1 += fw[c + 1];
            fw[c + 2] = __expf(fw[c + 2] - m);  s2 += fw[c + 2];
            fw[c + 3] = __expf(fw[c + 3] - m);  s3 += fw[c + 3];
        }
        float inv = __fdividef(1.0f, (s0 + s1) + (s2 + s3));
        #pragma unroll
        for (int c = 0; c < 32; ++c)
            acc[c] = fmaf(fw[c] * inv, u[c], acc[c]);
    }

    float4* outp = (float4*)&g_out[p * 32];
    #pragma unroll
    for (int c4 = 0; c4 < 8; ++c4)
        outp[c4] = make_float4(acc[c4 * 4 + 0], acc[c4 * 4 + 1],
                               acc[c4 * 4 + 2], acc[c4 * 4 + 3]);
}

extern "C" void kernel_launch(void* const* d_in, const int* in_sizes, int n_in,
                              void* d_out, int out_size) {
    const float* center = (const float*)d_in[0];
    const float* other  = (const float*)d_in[1];
    const float* w1     = (const float*)d_in[2];
    const float* b1     = (const float*)d_in[3];
    const float* w2     = (const float*)d_in[4];
    const float* b2     = (const float*)d_in[5];
    const float* wp1    = (const float*)d_in[6];
    const float* wpb1   = (const float*)d_in[7];
    const float* wp2    = (const float*)d_in[8];
    const float* wpb2   = (const float*)d_in[9];
    float* out = (float*)d_out;

    const int P = in_sizes[0] / 3;
    const int grid = (P + TPB - 1) / TPB;
    pae_kernel<<<grid, TPB>>>(center, other, w1, b1, w2, b2,
                              wp1, wpb1, wp2, wpb2, out, P);
}

// round 2
// speedup vs baseline: 1.0606x; 1.0606x over previous
#include <cuda_runtime.h>

#define TPB 128
typedef unsigned long long u64;

// ---------------- packed f32x2 helpers (sm_103a) ----------------
__device__ __forceinline__ u64 pk2(float x, float y) {
    u64 r; asm("mov.b64 %0, {%1,%2};" : "=l"(r) : "f"(x), "f"(y)); return r;
}
__device__ __forceinline__ void up2(u64 v, float& x, float& y) {
    asm("mov.b64 {%0,%1}, %2;" : "=f"(x), "=f"(y) : "l"(v));
}
__device__ __forceinline__ u64 fma2_(u64 a, u64 b, u64 c) {
    u64 d; asm("fma.rn.f32x2 %0, %1, %2, %3;" : "=l"(d) : "l"(a), "l"(b), "l"(c)); return d;
}
__device__ __forceinline__ u64 add2_(u64 a, u64 b) {
    u64 d; asm("add.rn.f32x2 %0, %1, %2;" : "=l"(d) : "l"(a), "l"(b)); return d;
}

// ---------------- constant-bank weight image layout (floats) ----------------
#define O_W1    0      // [6][3][16]          288
#define O_B1    288    // [6][16]             96
#define O_W2    384    // [6][16][32]         3072
#define O_TB    3456   // [2][32] b2p-b2k     64
#define O_UB    3520   // [2][32] b2p+b2v     64
#define O_BQ    3584   // [32]  b2 of q       32
#define O_WP1T  3616   // [64][32] transposed 2048
#define O_WPB1  5664   // [64]                64
#define O_WP2   5728   // [64][32]            2048
#define O_WPB2  7776   // [32]                32
#define N_CONST 7808   // 31232 bytes

__constant__ __align__(16) float c_all[N_CONST];
__device__   __align__(16) float g_prep[N_CONST];

// ---------------- prep: build folded/transposed weight image ----------------
__global__ void prep_kernel(const float* __restrict__ w1, const float* __restrict__ b1,
                            const float* __restrict__ w2, const float* __restrict__ b2,
                            const float* __restrict__ wp1, const float* __restrict__ wpb1,
                            const float* __restrict__ wp2, const float* __restrict__ wpb2) {
    const int t = threadIdx.x;
    for (int i = t; i < 288;  i += 256) g_prep[O_W1 + i] = w1[i];
    for (int i = t; i < 96;   i += 256) g_prep[O_B1 + i] = b1[i];
    for (int i = t; i < 3072; i += 256) g_prep[O_W2 + i] = w2[i];
    for (int i = t; i < 32;   i += 256) {
        float bp = b2[5 * 32 + i];
        g_prep[O_TB + i]      = bp - b2[1 * 32 + i];   // center variant: q - ck + pos biases
        g_prep[O_TB + 32 + i] = bp - b2[3 * 32 + i];   // other variant
        g_prep[O_UB + i]      = bp + b2[2 * 32 + i];   // v + pos biases (center)
        g_prep[O_UB + 32 + i] = bp + b2[4 * 32 + i];   // (other)
        g_prep[O_BQ + i]      = b2[i];
        g_prep[O_WPB2 + i]    = wpb2[i];
    }
    for (int i = t; i < 2048; i += 256) {
        int c = i >> 6, j = i & 63;                    // wp1 is [32][64]
        g_prep[O_WP1T + j * 32 + c] = wp1[i];
        g_prep[O_WP2 + i] = wp2[i];
    }
    for (int i = t; i < 64;   i += 256) g_prep[O_WPB1 + i] = wpb1[i];
}

// ---------------- per-row (neighbor) processing ----------------
// MK/MV: which stacked MLP supplies k and v (1,2 for center row; 3,4 for others).
template <int MK, int MV>
__device__ __forceinline__ void do_row(
    float x0, float x1, float x2, float d0, float d1, float d2,
    const u64* __restrict__ qv2,   // 16 pairs: q + (b2p - b2k) pre-added for this variant
    u64* __restrict__ acc2)
{
    u64 t2[16], u2[16];
    {
        const u64* ub = (const u64*)&c_all[O_UB + (MK == 1 ? 0 : 32)];
        #pragma unroll
        for (int i = 0; i < 16; ++i) { t2[i] = qv2[i]; u2[i] = ub[i]; }
    }

    // ---- fold k/v/pos hidden units into t (q-k+pos) and u (v+pos) ----
    #pragma unroll 4
    for (int j = 0; j < 16; ++j) {
        const float* w1k = &c_all[O_W1 + MK * 48];
        const float* w1v = &c_all[O_W1 + MV * 48];
        const float* w1p = &c_all[O_W1 + 5 * 48];
        float zk = c_all[O_B1 + MK * 16 + j] + x0 * w1k[j] + x1 * w1k[16 + j] + x2 * w1k[32 + j];
        float zv = c_all[O_B1 + MV * 16 + j] + x0 * w1v[j] + x1 * w1v[16 + j] + x2 * w1v[32 + j];
        float zp = c_all[O_B1 + 5 * 16 + j]  + d0 * w1p[j] + d1 * w1p[16 + j] + d2 * w1p[32 + j];
        float hk = fmaxf(zk, 0.01f * zk);
        float hv = fmaxf(zv, 0.01f * zv);
        float hp = fmaxf(zp, 0.01f * zp);
        u64 nhk2 = pk2(-hk, -hk), hv2 = pk2(hv, hv), hp2 = pk2(hp, hp);
        const u64* wk = (const u64*)&c_all[O_W2 + (MK * 16 + j) * 32];
        const u64* wv = (const u64*)&c_all[O_W2 + (MV * 16 + j) * 32];
        const u64* wp = (const u64*)&c_all[O_W2 + (5  * 16 + j) * 32];
        #pragma unroll
        for (int i = 0; i < 16; ++i) {
            u64 pw = wp[i];
            t2[i] = fma2_(nhk2, wk[i], fma2_(hp2, pw, t2[i]));
            u2[i] = fma2_(hv2,  wv[i], fma2_(hp2, pw, u2[i]));
        }
    }

    // ---- fea_weight = WP(t): 32 -> 64 (leaky) -> 32 ----
    u64 fw2[16];
    {
        const u64* wb = (const u64*)&c_all[O_WPB2];
        #pragma unroll
        for (int i = 0; i < 16; ++i) fw2[i] = wb[i];
    }
    #pragma unroll 4
    for (int j = 0; j < 64; ++j) {
        const u64* w1t = (const u64*)&c_all[O_WP1T + j * 32];
        u64 za = 0ull, zb = 0ull;
        #pragma unroll
        for (int i = 0; i < 16; i += 2) {
            za = fma2_(t2[i],     w1t[i],     za);
            zb = fma2_(t2[i + 1], w1t[i + 1], zb);
        }
        float a0, a1, b0, b1;
        up2(za, a0, a1); up2(zb, b0, b1);
        float z = c_all[O_WPB1 + j] + ((a0 + b0) + (a1 + b1));
        float g = fmaxf(z, 0.01f * z);
        u64 g2 = pk2(g, g);
        const u64* w2r = (const u64*)&c_all[O_WP2 + j * 32];
        #pragma unroll
        for (int i = 0; i < 16; ++i) fw2[i] = fma2_(g2, w2r[i], fw2[i]);
    }

    // ---- channel softmax + weighted accumulate ----
    float f[32];
    #pragma unroll
    for (int i = 0; i < 16; ++i) up2(fw2[i], f[2 * i], f[2 * i + 1]);
    float m0 = f[0], m1 = f[1], m2 = f[2], m3 = f[3];
    #pragma unroll
    for (int c = 4; c < 32; c += 4) {
        m0 = fmaxf(m0, f[c + 0]); m1 = fmaxf(m1, f[c + 1]);
        m2 = fmaxf(m2, f[c + 2]); m3 = fmaxf(m3, f[c + 3]);
    }
    float m = fmaxf(fmaxf(m0, m1), fmaxf(m2, m3));
    float s0 = 0.f, s1 = 0.f, s2 = 0.f, s3 = 0.f;
    #pragma unroll
    for (int c = 0; c < 32; c += 4) {
        f[c + 0] = __expf(f[c + 0] - m); s0 += f[c + 0];
        f[c + 1] = __expf(f[c + 1] - m); s1 += f[c + 1];
        f[c + 2] = __expf(f[c + 2] - m); s2 += f[c + 2];
        f[c + 3] = __expf(f[c + 3] - m); s3 += f[c + 3];
    }
    float inv = __fdividef(1.0f, (s0 + s1) + (s2 + s3));
    #pragma unroll
    for (int i = 0; i < 16; ++i)
        acc2[i] = fma2_(pk2(f[2 * i] * inv, f[2 * i + 1] * inv), u2[i], acc2[i]);
}

// ---------------- main kernel: one thread per point ----------------
__global__ void __launch_bounds__(TPB) pae_kernel(
    const float* __restrict__ g_center,   // [P,1,3]
    const float* __restrict__ g_other,    // [P,16,3]
    float* __restrict__ g_out,            // [P,32]
    int P)
{
    const int p = blockIdx.x * TPB + threadIdx.x;
    if (p >= P) return;

    const float cx = g_center[p * 3 + 0];
    const float cy = g_center[p * 3 + 1];
    const float cz = g_center[p * 3 + 2];

    // ---- q = MLP0(center) ----
    u64 q2[16];
    {
        const u64* bq = (const u64*)&c_all[O_BQ];
        #pragma unroll
        for (int i = 0; i < 16; ++i) q2[i] = bq[i];
        #pragma unroll 4
        for (int j = 0; j < 16; ++j) {
            float z = c_all[O_B1 + j] + cx * c_all[O_W1 + j] + cy * c_all[O_W1 + 16 + j]
                                      + cz * c_all[O_W1 + 32 + j];
            float h = fmaxf(z, 0.01f * z);
            u64 h2 = pk2(h, h);
            const u64* w = (const u64*)&c_all[O_W2 + j * 32];
            #pragma unroll
            for (int i = 0; i < 16; ++i) q2[i] = fma2_(h2, w[i], q2[i]);
        }
    }

    u64 acc2[16];
    #pragma unroll
    for (int i = 0; i < 16; ++i) acc2[i] = 0ull;

    // ---- center row (k=ck via MLP1, v=cv via MLP2, fea_minus = 0) ----
    {
        u64 qc2[16];
        const u64* tb = (const u64*)&c_all[O_TB];
        #pragma unroll
        for (int i = 0; i < 16; ++i) qc2[i] = add2_(q2[i], tb[i]);
        do_row<1, 2>(cx, cy, cz, 0.f, 0.f, 0.f, qc2, acc2);
    }

    // ---- pre-add neighbor-variant biases into q ----
    {
        const u64* tb = (const u64*)&c_all[O_TB + 32];
        #pragma unroll
        for (int i = 0; i < 16; ++i) q2[i] = add2_(q2[i], tb[i]);
    }

    // ---- 16 neighbor rows (k=ok via MLP3, v=ov via MLP4) ----
    const float* obase = g_other + p * 48;
    float nx0 = obase[0], nx1 = obase[1], nx2 = obase[2];
    for (int r = 0; r < 16; ++r) {
        float x0 = nx0, x1 = nx1, x2 = nx2;
        if (r < 15) {   // prefetch next neighbor
            const float* op = obase + (r + 1) * 3;
            nx0 = op[0]; nx1 = op[1]; nx2 = op[2];
        }
        do_row<3, 4>(x0, x1, x2, cx - x0, cy - x1, cz - x2, q2, acc2);
    }

    // ---- store [32] as 8x 16B ----
    ulonglong2* outp = (ulonglong2*)&g_out[p * 32];
    #pragma unroll
    for (int i = 0; i < 8; ++i)
        outp[i] = make_ulonglong2(acc2[2 * i], acc2[2 * i + 1]);
}

extern "C" void kernel_launch(void* const* d_in, const int* in_sizes, int n_in,
                              void* d_out, int out_size) {
    const float* center = (const float*)d_in[0];
    const float* other  = (const float*)d_in[1];
    const float* w1     = (const float*)d_in[2];
    const float* b1     = (const float*)d_in[3];
    const float* w2     = (const float*)d_in[4];
    const float* b2     = (const float*)d_in[5];
    const float* wp1    = (const float*)d_in[6];
    const float* wpb1   = (const float*)d_in[7];
    const float* wp2    = (const float*)d_in[8];
    const float* wpb2   = (const float*)d_in[9];
    float* out = (float*)d_out;

    const int P = in_sizes[0] / 3;

    prep_kernel<<<1, 256>>>(w1, b1, w2, b2, wp1, wpb1, wp2, wpb2);

    void* prep_addr = nullptr;
    cudaGetSymbolAddress(&prep_addr, g_prep);
    cudaMemcpyToSymbolAsync(c_all, prep_addr, N_CONST * sizeof(float), 0,
                            cudaMemcpyDeviceToDevice, 0);

    const int grid = (P + TPB - 1) / TPB;
    pae_kernel<<<grid, TPB>>>(center, other, out, P);
}

// round 5
// speedup vs baseline: 1.1285x; 1.0641x over previous
#include <cuda_runtime.h>

#define TPB 128
typedef unsigned long long u64;

// ---------------- packed f32x2 helpers (sm_103a) ----------------
__device__ __forceinline__ u64 pk2(float x, float y) {
    u64 r; asm("mov.b64 %0, {%1,%2};" : "=l"(r) : "f"(x), "f"(y)); return r;
}
__device__ __forceinline__ void up2(u64 v, float& x, float& y) {
    asm("mov.b64 {%0,%1}, %2;" : "=f"(x), "=f"(y) : "l"(v));
}
__device__ __forceinline__ u64 fma2_(u64 a, u64 b, u64 c) {
    u64 d; asm("fma.rn.f32x2 %0, %1, %2, %3;" : "=l"(d) : "l"(a), "l"(b), "l"(c)); return d;
}
__device__ __forceinline__ u64 add2_(u64 a, u64 b) {
    u64 d; asm("add.rn.f32x2 %0, %1, %2;" : "=l"(d) : "l"(a), "l"(b)); return d;
}

// ---------------- constant-bank weight image layout (floats) ----------------
#define O_W1    0      // [6][3][16]          288
#define O_B1    288    // [6][16]             96
#define O_W2    384    // [6][16][32]         3072
#define O_TBO   3456   // [32] b2p-b2k (other variant, folded into parked q)
#define O_DTB   3488   // [32] b2k_other-b2k_center (center delta on parked q)
#define O_UB    3520   // [2][32] b2p+b2v     64
#define O_BQ    3584   // [32]  b2 of q       32
#define O_WP1T  3616   // [64][32] transposed 2048
#define O_WPB1  5664   // [64]                64
#define O_WP2   5728   // [64][32]            2048
#define O_WPB2  7776   // [32]                32
#define N_CONST 7808   // 31232 bytes

__constant__ __align__(16) float c_all[N_CONST];
__device__   __align__(16) float g_prep[N_CONST];

// ---------------- prep: build folded/transposed weight image ----------------
__global__ void prep_kernel(const float* __restrict__ w1, const float* __restrict__ b1,
                            const float* __restrict__ w2, const float* __restrict__ b2,
                            const float* __restrict__ wp1, const float* __restrict__ wpb1,
                            const float* __restrict__ wp2, const float* __restrict__ wpb2) {
    const int t = threadIdx.x;
    for (int i = t; i < 288;  i += 256) g_prep[O_W1 + i] = w1[i];
    for (int i = t; i < 96;   i += 256) g_prep[O_B1 + i] = b1[i];
    for (int i = t; i < 3072; i += 256) g_prep[O_W2 + i] = w2[i];
    for (int i = t; i < 32;   i += 256) {
        float bp = b2[5 * 32 + i];
        g_prep[O_TBO + i]     = bp - b2[3 * 32 + i];           // q + this parked in smem
        g_prep[O_DTB + i]     = b2[3 * 32 + i] - b2[1 * 32 + i]; // parked + this = center t-init
        g_prep[O_UB + i]      = bp + b2[2 * 32 + i];           // v + pos biases (center)
        g_prep[O_UB + 32 + i] = bp + b2[4 * 32 + i];           // (other)
        g_prep[O_BQ + i]      = b2[i];
        g_prep[O_WPB2 + i]    = wpb2[i];
    }
    for (int i = t; i < 2048; i += 256) {
        int c = i >> 6, j = i & 63;                            // wp1 is [32][64]
        g_prep[O_WP1T + j * 32 + c] = wp1[i];
        g_prep[O_WP2 + i] = wp2[i];
    }
    for (int i = t; i < 64;   i += 256) g_prep[O_WPB1 + i] = wpb1[i];
}

// ---------------- per-row (neighbor) processing ----------------
// MK/MV: which stacked MLP supplies k and v. CENTER: apply dtb to parked q.
template <int MK, int MV, bool CENTER>
__device__ __forceinline__ void do_row(
    float x0, float x1, float x2, float d0, float d1, float d2,
    const u64 (*s_q)[TPB], int tid,
    u64* __restrict__ acc2)
{
    u64 t2[16], u2[16];
    {
        const u64* ub  = (const u64*)&c_all[O_UB + (CENTER ? 0 : 32)];
        const u64* dtb = (const u64*)&c_all[O_DTB];
        #pragma unroll
        for (int i = 0; i < 16; ++i) {
            u64 v = s_q[i][tid];
            if (CENTER) v = add2_(v, dtb[i]);
            t2[i] = v;
            u2[i] = ub[i];
        }
    }

    // ---- fold k/v/pos hidden units into t (q-k+pos) and u (v+pos) ----
    #pragma unroll 4
    for (int j = 0; j < 16; ++j) {
        const float* w1k = &c_all[O_W1 + MK * 48];
        const float* w1v = &c_all[O_W1 + MV * 48];
        const float* w1p = &c_all[O_W1 + 5 * 48];
        float zk = c_all[O_B1 + MK * 16 + j] + x0 * w1k[j] + x1 * w1k[16 + j] + x2 * w1k[32 + j];
        float zv = c_all[O_B1 + MV * 16 + j] + x0 * w1v[j] + x1 * w1v[16 + j] + x2 * w1v[32 + j];
        float zp = c_all[O_B1 + 5 * 16 + j]  + d0 * w1p[j] + d1 * w1p[16 + j] + d2 * w1p[32 + j];
        float hk = fmaxf(zk, 0.01f * zk);
        float hv = fmaxf(zv, 0.01f * zv);
        float hp = fmaxf(zp, 0.01f * zp);
        u64 nhk2 = pk2(-hk, -hk), hv2 = pk2(hv, hv), hp2 = pk2(hp, hp);
        const u64* wk = (const u64*)&c_all[O_W2 + (MK * 16 + j) * 32];
        const u64* wv = (const u64*)&c_all[O_W2 + (MV * 16 + j) * 32];
        const u64* wp = (const u64*)&c_all[O_W2 + (5  * 16 + j) * 32];
        #pragma unroll
        for (int i = 0; i < 16; ++i) {
            u64 pw = wp[i];
            t2[i] = fma2_(nhk2, wk[i], fma2_(hp2, pw, t2[i]));
            u2[i] = fma2_(hv2,  wv[i], fma2_(hp2, pw, u2[i]));
        }
    }

    // ---- fea_weight = WP(t): 32 -> 64 (leaky) -> 32 ----
    u64 fw2[16];
    {
        const u64* wb = (const u64*)&c_all[O_WPB2];
        #pragma unroll
        for (int i = 0; i < 16; ++i) fw2[i] = wb[i];
    }
    #pragma unroll 4
    for (int j = 0; j < 64; ++j) {
        const u64* w1t = (const u64*)&c_all[O_WP1T + j * 32];
        u64 za = 0ull, zb = 0ull;
        #pragma unroll
        for (int i = 0; i < 16; i += 2) {
            za = fma2_(t2[i],     w1t[i],     za);
            zb = fma2_(t2[i + 1], w1t[i + 1], zb);
        }
        float a0, a1, b0, b1;
        up2(za, a0, a1); up2(zb, b0, b1);
        float z = c_all[O_WPB1 + j] + ((a0 + b0) + (a1 + b1));
        float g = fmaxf(z, 0.01f * z);
        u64 g2 = pk2(g, g);
        const u64* w2r = (const u64*)&c_all[O_WP2 + j * 32];
        #pragma unroll
        for (int i = 0; i < 16; ++i) fw2[i] = fma2_(g2, w2r[i], fw2[i]);
    }

    // ---- channel softmax + weighted accumulate ----
    float f[32];
    #pragma unroll
    for (int i = 0; i < 16; ++i) up2(fw2[i], f[2 * i], f[2 * i + 1]);
    float m0 = f[0], m1 = f[1], m2 = f[2], m3 = f[3];
    #pragma unroll
    for (int c = 4; c < 32; c += 4) {
        m0 = fmaxf(m0, f[c + 0]); m1 = fmaxf(m1, f[c + 1]);
        m2 = fmaxf(m2, f[c + 2]); m3 = fmaxf(m3, f[c + 3]);
    }
    float m = fmaxf(fmaxf(m0, m1), fmaxf(m2, m3));
    float s0 = 0.f, s1 = 0.f, s2 = 0.f, s3 = 0.f;
    #pragma unroll
    for (int c = 0; c < 32; c += 4) {
        f[c + 0] = __expf(f[c + 0] - m); s0 += f[c + 0];
        f[c + 1] = __expf(f[c + 1] - m); s1 += f[c + 1];
        f[c + 2] = __expf(f[c + 2] - m); s2 += f[c + 2];
        f[c + 3] = __expf(f[c + 3] - m); s3 += f[c + 3];
    }
    float inv = __fdividef(1.0f, (s0 + s1) + (s2 + s3));
    #pragma unroll
    for (int i = 0; i < 16; ++i)
        acc2[i] = fma2_(pk2(f[2 * i] * inv, f[2 * i + 1] * inv), u2[i], acc2[i]);
}

// ---------------- main kernel: one thread per point ----------------
__global__ void __launch_bounds__(TPB, 3) pae_kernel(
    const float* __restrict__ g_center,   // [P,1,3]
    const float* __restrict__ g_other,    // [P,16,3]
    float* __restrict__ g_out,            // [P,32]
    int P)
{
    // Parked (q + tb_other) per thread: transposed layout, conflict-free LDS/STS.64
    __shared__ u64 s_q[16][TPB];

    const int tid = threadIdx.x;
    const int p = blockIdx.x * TPB + tid;
    if (p >= P) return;

    const float cx = g_center[p * 3 + 0];
    const float cy = g_center[p * 3 + 1];
    const float cz = g_center[p * 3 + 2];

    // ---- q = MLP0(center), then fold in tb_other and park in smem ----
    {
        u64 q2[16];
        const u64* bq = (const u64*)&c_all[O_BQ];
        #pragma unroll
        for (int i = 0; i < 16; ++i) q2[i] = bq[i];
        #pragma unroll 4
        for (int j = 0; j < 16; ++j) {
            float z = c_all[O_B1 + j] + cx * c_all[O_W1 + j] + cy * c_all[O_W1 + 16 + j]
                                      + cz * c_all[O_W1 + 32 + j];
            float h = fmaxf(z, 0.01f * z);
            u64 h2 = pk2(h, h);
            const u64* w = (const u64*)&c_all[O_W2 + j * 32];
            #pragma unroll
            for (int i = 0; i < 16; ++i) q2[i] = fma2_(h2, w[i], q2[i]);
        }
        const u64* tb = (const u64*)&c_all[O_TBO];
        #pragma unroll
        for (int i = 0; i < 16; ++i) s_q[i][tid] = add2_(q2[i], tb[i]);
    }

    u64 acc2[16];
    #pragma unroll
    for (int i = 0; i < 16; ++i) acc2[i] = 0ull;

    // ---- center row (k=ck via MLP1, v=cv via MLP2, fea_minus = 0) ----
    do_row<1, 2, true>(cx, cy, cz, 0.f, 0.f, 0.f, s_q, tid, acc2);

    // ---- 16 neighbor rows (k=ok via MLP3, v=ov via MLP4) ----
    const float* obase = g_other + p * 48;
    float nx0 = obase[0], nx1 = obase[1], nx2 = obase[2];
    for (int r = 0; r < 16; ++r) {
        float x0 = nx0, x1 = nx1, x2 = nx2;
        if (r < 15) {   // prefetch next neighbor
            const float* op = obase + (r + 1) * 3;
            nx0 = op[0]; nx1 = op[1]; nx2 = op[2];
        }
        do_row<3, 4, false>(x0, x1, x2, cx - x0, cy - x1, cz - x2, s_q, tid, acc2);
    }

    // ---- store [32] as 8x 16B ----
    ulonglong2* outp = (ulonglong2*)&g_out[p * 32];
    #pragma unroll
    for (int i = 0; i < 8; ++i)
        outp[i] = make_ulonglong2(acc2[2 * i], acc2[2 * i + 1]);
}

extern "C" void kernel_launch(void* const* d_in, const int* in_sizes, int n_in,
                              void* d_out, int out_size) {
    const float* center = (const float*)d_in[0];
    const float* other  = (const float*)d_in[1];
    const float* w1     = (const float*)d_in[2];
    const float* b1     = (const float*)d_in[3];
    const float* w2     = (const float*)d_in[4];
    const float* b2     = (const float*)d_in[5];
    const float* wp1    = (const float*)d_in[6];
    const float* wpb1   = (const float*)d_in[7];
    const float* wp2    = (const float*)d_in[8];
    const float* wpb2   = (const float*)d_in[9];
    float* out = (float*)d_out;

    const int P = in_sizes[0] / 3;

    prep_kernel<<<1, 256>>>(w1, b1, w2, b2, wp1, wpb1, wp2, wpb2);

    void* prep_addr = nullptr;
    cudaGetSymbolAddress(&prep_addr, g_prep);
    cudaMemcpyToSymbolAsync(c_all, prep_addr, N_CONST * sizeof(float), 0,
                            cudaMemcpyDeviceToDevice, 0);

    const int grid = (P + TPB - 1) / TPB;
    pae_kernel<<<grid, TPB>>>(center, other, out, P);
}